// round 1
// baseline (speedup 1.0000x reference)
#include <cuda_runtime.h>
#include <cuda_bf16.h>

#define NN 50000
#define NE 600000
#define F  128
#define NT 4
#define KTOT (5*F)   // 640

// ---------------- scratch (static device globals; no allocation) ------------
__device__ float g_s[(size_t)NT * NN * F];   // per-type segment sums -> means
__device__ int   g_cnt[NT * NN];             // per-type in-degree (layer-invariant)
__device__ float g_h1[(size_t)NN * F];       // hidden activations after layer 1
__device__ float g_W1[KTOT * F];             // [Wself_bar ; Wn1/4 ...]
__device__ float g_W2[KTOT * F];
__device__ float g_bb1[F];
__device__ float g_bb2[F];

// ---------------- weight prep: fold the type-mean into the weights ----------
__global__ void prep_weights(const float* __restrict__ Ws1, const float* __restrict__ Wn1,
                             const float* __restrict__ b1,
                             const float* __restrict__ Ws2, const float* __restrict__ Wn2,
                             const float* __restrict__ b2) {
    int idx = blockIdx.x * blockDim.x + threadIdx.x;   // over KTOT*F = 81920
    if (idx >= KTOT * F) return;
    int k = idx / F, j = idx % F;
    float w1, w2;
    if (k < F) {
        float a1 = 0.f, a2 = 0.f;
        #pragma unroll
        for (int t = 0; t < NT; t++) {
            a1 += Ws1[(t * F + k) * F + j];
            a2 += Ws2[(t * F + k) * F + j];
        }
        w1 = a1 * 0.25f; w2 = a2 * 0.25f;
    } else {
        int t = (k - F) >> 7;
        int kk = (k - F) & 127;
        w1 = Wn1[(t * F + kk) * F + j] * 0.25f;
        w2 = Wn2[(t * F + kk) * F + j] * 0.25f;
    }
    g_W1[idx] = w1; g_W2[idx] = w2;
    if (idx < F) {
        float s1 = 0.f, s2 = 0.f;
        #pragma unroll
        for (int t = 0; t < NT; t++) { s1 += b1[t * F + idx]; s2 += b2[t * F + idx]; }
        g_bb1[idx] = s1 * 0.25f; g_bb2[idx] = s2 * 0.25f;
    }
}

// ---------------- zeroing ----------------------------------------------------
__global__ void zero_s() {
    size_t i = (size_t)blockIdx.x * blockDim.x + threadIdx.x;  // float4 index
    size_t n4 = (size_t)NT * NN * F / 4;
    if (i < n4) reinterpret_cast<float4*>(g_s)[i] = make_float4(0.f, 0.f, 0.f, 0.f);
}

__global__ void zero_cnt() {
    int i = blockIdx.x * blockDim.x + threadIdx.x;
    if (i < NT * NN) g_cnt[i] = 0;
}

// ---------------- counts (once; identical for both layers) -------------------
__global__ void count_edges(const int* __restrict__ ei, const int* __restrict__ et) {
    int e = blockIdx.x * blockDim.x + threadIdx.x;
    if (e >= NE) return;
    atomicAdd(&g_cnt[et[e] * NN + ei[NE + e]], 1);
}

// ---------------- edge scatter: one warp per edge ----------------------------
__global__ void scatter_edges(const float* __restrict__ h,
                              const int* __restrict__ ei, const int* __restrict__ et) {
    int gtid = blockIdx.x * blockDim.x + threadIdx.x;
    int e = gtid >> 5;
    int lane = threadIdx.x & 31;
    if (e >= NE) return;
    int src = ei[e];
    int dst = ei[NE + e];
    int t = et[e];
    float4 v = *reinterpret_cast<const float4*>(h + (size_t)src * F + lane * 4);
    float* p = g_s + ((size_t)(t * NN + dst)) * F + lane * 4;
    asm volatile("red.global.add.v4.f32 [%0], {%1,%2,%3,%4};"
                 :: "l"(p), "f"(v.x), "f"(v.y), "f"(v.z), "f"(v.w) : "memory");
}

// ---------------- s -> mean (divide by max(cnt,1)); one warp per (t,node) ----
__global__ void scale_means() {
    int gtid = blockIdx.x * blockDim.x + threadIdx.x;
    int row = gtid >> 5;
    int lane = threadIdx.x & 31;
    if (row >= NT * NN) return;
    int c = g_cnt[row];
    float inv = 1.0f / (float)(c > 1 ? c : 1);
    float4* p = reinterpret_cast<float4*>(g_s + (size_t)row * F) + lane;
    float4 v = *p;
    v.x *= inv; v.y *= inv; v.z *= inv; v.w *= inv;
    *p = v;
}

// ---------------- GEMM: out[N,128] = [A0 | means] (N x 640) @ W (640 x 128) --
// Block tile 64x128, BK=16, 256 threads, thread tile 4x8.
__global__ __launch_bounds__(256)
void gemm_640(const float* __restrict__ A0, const float* __restrict__ W,
              const float* __restrict__ bias, float* __restrict__ out) {
    __shared__ float As[16][64];   // [k][m]
    __shared__ float Bs[16][128];  // [k][n]

    int m0 = blockIdx.x * 64;
    int tid = threadIdx.x;
    int tr = tid >> 4;          // 0..15 -> rows tr*4 .. tr*4+3
    int tc = tid & 15;          // 0..15 -> cols tc*8 .. tc*8+7

    // A-load mapping: 64 rows x 16 k per tile; thread loads one float4
    int rowA = tid >> 2;               // 0..63
    int kvA  = (tid & 3) * 4;          // 0,4,8,12
    int n = m0 + rowA;
    bool valid = (n < NN);

    // B-load mapping: 16 rows x 128 cols; thread loads rows rB and rB+8
    int rB = tid >> 5;                 // 0..7
    int cB = (tid & 31) * 4;           // 0..124

    float acc[4][8];
    #pragma unroll
    for (int i = 0; i < 4; i++)
        #pragma unroll
        for (int j = 0; j < 8; j++) acc[i][j] = 0.f;

    for (int kk = 0; kk < KTOT; kk += 16) {
        // A tile source: segment 0 = A0 (h), segments 1..4 = means in g_s
        int seg  = kk >> 7;
        int koff = kk & 127;
        const float* arow = (seg == 0)
            ? (A0 + (size_t)n * F)
            : (g_s + ((size_t)((seg - 1) * NN + n)) * F);
        float4 av = make_float4(0.f, 0.f, 0.f, 0.f);
        if (valid) av = *reinterpret_cast<const float4*>(arow + koff + kvA);
        As[kvA + 0][rowA] = av.x;
        As[kvA + 1][rowA] = av.y;
        As[kvA + 2][rowA] = av.z;
        As[kvA + 3][rowA] = av.w;

        float4 b0 = *reinterpret_cast<const float4*>(W + (size_t)(kk + rB) * F + cB);
        float4 b1 = *reinterpret_cast<const float4*>(W + (size_t)(kk + rB + 8) * F + cB);
        *reinterpret_cast<float4*>(&Bs[rB][cB])     = b0;
        *reinterpret_cast<float4*>(&Bs[rB + 8][cB]) = b1;

        __syncthreads();

        #pragma unroll
        for (int k = 0; k < 16; k++) {
            float4 a  = *reinterpret_cast<float4*>(&As[k][tr * 4]);
            float4 bA = *reinterpret_cast<float4*>(&Bs[k][tc * 8]);
            float4 bB = *reinterpret_cast<float4*>(&Bs[k][tc * 8 + 4]);
            float am[4] = {a.x, a.y, a.z, a.w};
            float bm[8] = {bA.x, bA.y, bA.z, bA.w, bB.x, bB.y, bB.z, bB.w};
            #pragma unroll
            for (int i = 0; i < 4; i++)
                #pragma unroll
                for (int j = 0; j < 8; j++)
                    acc[i][j] = fmaf(am[i], bm[j], acc[i][j]);
        }
        __syncthreads();
    }

    // epilogue: + bias, store
    float bb[8];
    #pragma unroll
    for (int j = 0; j < 8; j++) bb[j] = bias[tc * 8 + j];
    #pragma unroll
    for (int i = 0; i < 4; i++) {
        int row = m0 + tr * 4 + i;
        if (row < NN) {
            float4 o0 = make_float4(acc[i][0] + bb[0], acc[i][1] + bb[1],
                                    acc[i][2] + bb[2], acc[i][3] + bb[3]);
            float4 o1 = make_float4(acc[i][4] + bb[4], acc[i][5] + bb[5],
                                    acc[i][6] + bb[6], acc[i][7] + bb[7]);
            *reinterpret_cast<float4*>(out + (size_t)row * F + tc * 8)     = o0;
            *reinterpret_cast<float4*>(out + (size_t)row * F + tc * 8 + 4) = o1;
        }
    }
}

// ---------------- L2 normalize + relu, in place on g_h1; one warp per row ----
__global__ void norm_relu() {
    int gtid = blockIdx.x * blockDim.x + threadIdx.x;
    int row = gtid >> 5;
    int lane = threadIdx.x & 31;
    if (row >= NN) return;
    float4* p = reinterpret_cast<float4*>(g_h1 + (size_t)row * F) + lane;
    float4 v = *p;
    float ss = v.x * v.x + v.y * v.y + v.z * v.z + v.w * v.w;
    #pragma unroll
    for (int off = 16; off > 0; off >>= 1)
        ss += __shfl_xor_sync(0xFFFFFFFFu, ss, off);
    float nrm = sqrtf(ss);
    float inv = 1.0f / fmaxf(nrm, 1e-12f);
    v.x = fmaxf(v.x * inv, 0.f);
    v.y = fmaxf(v.y * inv, 0.f);
    v.z = fmaxf(v.z * inv, 0.f);
    v.w = fmaxf(v.w * inv, 0.f);
    *p = v;
}

// ---------------- launch ------------------------------------------------------
extern "C" void kernel_launch(void* const* d_in, const int* in_sizes, int n_in,
                              void* d_out, int out_size) {
    const float* x   = (const float*)d_in[0];
    const float* Ws1 = (const float*)d_in[1];
    const float* Wn1 = (const float*)d_in[2];
    const float* b1  = (const float*)d_in[3];
    const float* Ws2 = (const float*)d_in[4];
    const float* Wn2 = (const float*)d_in[5];
    const float* b2  = (const float*)d_in[6];
    const int*   ei  = (const int*)d_in[7];
    const int*   et  = (const int*)d_in[8];
    float* out = (float*)d_out;

    void *p_h1, *p_W1, *p_W2, *p_bb1, *p_bb2;
    cudaGetSymbolAddress(&p_h1, g_h1);
    cudaGetSymbolAddress(&p_W1, g_W1);
    cudaGetSymbolAddress(&p_W2, g_W2);
    cudaGetSymbolAddress(&p_bb1, g_bb1);
    cudaGetSymbolAddress(&p_bb2, g_bb2);

    const int ZS_BLOCKS = (int)(((size_t)NT * NN * F / 4 + 255) / 256);
    const int SC_BLOCKS = (int)(((size_t)NE * 32 + 255) / 256);
    const int SM_BLOCKS = (int)(((size_t)NT * NN * 32 + 255) / 256);
    const int GM_BLOCKS = (NN + 63) / 64;
    const int NR_BLOCKS = (int)(((size_t)NN * 32 + 255) / 256);

    prep_weights<<<(KTOT * F + 255) / 256, 256>>>(Ws1, Wn1, b1, Ws2, Wn2, b2);
    zero_cnt<<<(NT * NN + 255) / 256, 256>>>();
    count_edges<<<(NE + 255) / 256, 256>>>(ei, et);

    // ---- layer 1 ----
    zero_s<<<ZS_BLOCKS, 256>>>();
    scatter_edges<<<SC_BLOCKS, 256>>>(x, ei, et);
    scale_means<<<SM_BLOCKS, 256>>>();
    gemm_640<<<GM_BLOCKS, 256>>>(x, (const float*)p_W1, (const float*)p_bb1, (float*)p_h1);
    norm_relu<<<NR_BLOCKS, 256>>>();

    // ---- layer 2 ----
    zero_s<<<ZS_BLOCKS, 256>>>();
    scatter_edges<<<SC_BLOCKS, 256>>>((const float*)p_h1, ei, et);
    scale_means<<<SM_BLOCKS, 256>>>();
    gemm_640<<<GM_BLOCKS, 256>>>((const float*)p_h1, (const float*)p_W2, (const float*)p_bb2, out);
}